// round 1
// baseline (speedup 1.0000x reference)
#include <cuda_runtime.h>
#include <math.h>

#define MAXB   262144
#define HDIM   256
#define EPSF   1e-6f
#define BM     64
#define TPB    256

// Scratch (static device allocs are allowed; cudaMalloc is not).
__device__ float g_feats[MAXB * 32];   // 25 real features, padded to 32 (zeros)
__device__ float g_R[MAXB * 9];        // polar rotation per particle
__device__ float g_c1[HDIM];           // b1 + latent @ W1[25:153]

__device__ __forceinline__ float gelu_exact(float x) {
    return 0.5f * x * (1.0f + erff(x * 0.70710678118654752f));
}

// ---------------------------------------------------------------------------
// Fold the constant latent embedding into layer-1 bias: c1 = b1 + emb[traj] @ W1[25:,:]
// ---------------------------------------------------------------------------
__global__ void c1_kernel(const float* __restrict__ emb, const int* __restrict__ traj,
                          const float* __restrict__ W1, const float* __restrict__ b1) {
    int n = threadIdx.x;               // 0..255
    int t = traj[0];
    const float* lat = emb + t * 128;
    float s = b1[n];
    #pragma unroll 4
    for (int d = 0; d < 128; ++d)
        s = fmaf(__ldg(lat + d), __ldg(W1 + (25 + d) * HDIM + n), s);
    g_c1[n] = s;
}

// ---------------------------------------------------------------------------
// Per-particle front-end: polar rotation (Newton), singular values (trig eigen
// of FtF), strain features, C passthrough.
// ---------------------------------------------------------------------------
__global__ void feat_kernel(const float* __restrict__ Fg, const float* __restrict__ Cg, int B) {
    int i = blockIdx.x * blockDim.x + threadIdx.x;
    if (i >= B) return;

    float f[9];
    #pragma unroll
    for (int k = 0; k < 9; ++k) f[k] = Fg[i * 9 + k];

    // --- polar decomposition via determinant-scaled Newton ---
    float r[9];
    #pragma unroll
    for (int k = 0; k < 9; ++k) r[k] = f[k];
    #pragma unroll
    for (int it = 0; it < 5; ++it) {
        float c00 = r[4]*r[8] - r[5]*r[7];
        float c01 = r[5]*r[6] - r[3]*r[8];
        float c02 = r[3]*r[7] - r[4]*r[6];
        float c10 = r[2]*r[7] - r[1]*r[8];
        float c11 = r[0]*r[8] - r[2]*r[6];
        float c12 = r[1]*r[6] - r[0]*r[7];
        float c20 = r[1]*r[5] - r[2]*r[4];
        float c21 = r[2]*r[3] - r[0]*r[5];
        float c22 = r[0]*r[4] - r[1]*r[3];
        float det = r[0]*c00 + r[1]*c01 + r[2]*c02;
        float ad  = fmaxf(fabsf(det), 1e-30f);
        float mu  = rcbrtf(ad);              // |det|^(-1/3)
        float s2  = 0.5f * mu;
        float s3  = 0.5f / (mu * det);       // (1/mu) * R^{-T} = cof/(mu*det)
        float n0 = s2*r[0] + s3*c00, n1 = s2*r[1] + s3*c01, n2 = s2*r[2] + s3*c02;
        float n3 = s2*r[3] + s3*c10, n4 = s2*r[4] + s3*c11, n5 = s2*r[5] + s3*c12;
        float n6 = s2*r[6] + s3*c20, n7 = s2*r[7] + s3*c21, n8 = s2*r[8] + s3*c22;
        r[0]=n0; r[1]=n1; r[2]=n2; r[3]=n3; r[4]=n4; r[5]=n5; r[6]=n6; r[7]=n7; r[8]=n8;
    }

    // --- A = F^T F (symmetric) ---
    float a00 = f[0]*f[0] + f[3]*f[3] + f[6]*f[6];
    float a01 = f[0]*f[1] + f[3]*f[4] + f[6]*f[7];
    float a02 = f[0]*f[2] + f[3]*f[5] + f[6]*f[8];
    float a11 = f[1]*f[1] + f[4]*f[4] + f[7]*f[7];
    float a12 = f[1]*f[2] + f[4]*f[5] + f[7]*f[8];
    float a22 = f[2]*f[2] + f[5]*f[5] + f[8]*f[8];

    // --- eigenvalues of A (descending) via trigonometric cubic ---
    float q  = (a00 + a11 + a22) * (1.0f / 3.0f);
    float d0 = a00 - q, d1 = a11 - q, d2 = a22 - q;
    float p2 = d0*d0 + d1*d1 + d2*d2 + 2.0f * (a01*a01 + a02*a02 + a12*a12);
    float e1, e2, e3;
    if (p2 < 1e-18f) {
        e1 = e2 = e3 = q;
    } else {
        float p    = sqrtf(p2 * (1.0f / 6.0f));
        float invp = 1.0f / p;
        float b00 = d0 * invp, b11 = d1 * invp, b22 = d2 * invp;
        float b01 = a01 * invp, b02 = a02 * invp, b12 = a12 * invp;
        float detB = b00*(b11*b22 - b12*b12) - b01*(b01*b22 - b12*b02) + b02*(b01*b12 - b11*b02);
        float rr = fminf(fmaxf(0.5f * detB, -1.0f), 1.0f);
        float phi = acosf(rr) * (1.0f / 3.0f);
        e1 = q + 2.0f * p * cosf(phi);
        e3 = q + 2.0f * p * cosf(phi + 2.09439510239319549f);   // +2pi/3
        e2 = 3.0f * q - e1 - e3;
    }
    float s1 = sqrtf(fmaxf(e1, 0.0f));
    float s2v = sqrtf(fmaxf(e2, 0.0f));
    float s3v = sqrtf(fmaxf(e3, 0.0f));

    float detF = f[0]*(f[4]*f[8] - f[5]*f[7])
               - f[1]*(f[3]*f[8] - f[5]*f[6])
               + f[2]*(f[3]*f[7] - f[4]*f[6]);
    float f00c = fmaxf(f[0], EPSF);

    float* fp = g_feats + (size_t)i * 32;
    fp[0]  = s1  - 1.0f;
    fp[1]  = s2v - 1.0f;
    fp[2]  = s3v - 1.0f;
    fp[3]  = a00 - 1.0f;  fp[4]  = a01;         fp[5]  = a02;
    fp[6]  = a01;         fp[7]  = a11 - 1.0f;  fp[8]  = a12;
    fp[9]  = a02;         fp[10] = a12;         fp[11] = a22 - 1.0f;
    fp[12] = detF - 1.0f;
    fp[13] = logf(detF) - 1.0f;
    fp[14] = f00c - 1.0f;
    fp[15] = logf(f00c) - 1.0f;
    #pragma unroll
    for (int j = 0; j < 9; ++j) fp[16 + j] = Cg[i * 9 + j];
    #pragma unroll
    for (int j = 25; j < 32; ++j) fp[j] = 0.0f;

    #pragma unroll
    for (int k = 0; k < 9; ++k) g_R[i * 9 + k] = r[k];
}

// ---------------------------------------------------------------------------
// Fused MLP: one block = 64 rows; activations live in smem across all layers.
// 256 threads; 8x8 register tile per thread for the 256-wide layers.
// ---------------------------------------------------------------------------
template <bool DOGELU>
__device__ __forceinline__ void layer_pass(
    const float* __restrict__ W, const float* __restrict__ bias,
    int Kpad, int Kvalid, float* sAct, float* sW, int tid)
{
    const int tn = tid & 31, tm = tid >> 5;
    const int colBase = tn * 8, rowBase = tm * 8;

    float acc[64];
    #pragma unroll
    for (int z = 0; z < 64; ++z) acc[z] = 0.0f;

    const int wr = tid >> 5;          // warp w stages W row (k0 + w)
    const int wc = (tid & 31) * 8;

    for (int k0 = 0; k0 < Kpad; k0 += 8) {
        int krow = k0 + wr;
        float4 v0, v1;
        if (krow < Kvalid) {
            const float4* wrow = (const float4*)(W + (size_t)krow * 256 + wc);
            v0 = wrow[0]; v1 = wrow[1];
        } else {
            v0 = make_float4(0.f, 0.f, 0.f, 0.f);
            v1 = v0;
        }
        ((float4*)(sW + wr * 256 + wc))[0] = v0;
        ((float4*)(sW + wr * 256 + wc))[1] = v1;
        __syncthreads();

        #pragma unroll
        for (int kk = 0; kk < 8; ++kk) {
            float av[8];
            #pragma unroll
            for (int im = 0; im < 8; ++im)
                av[im] = sAct[(rowBase + im) * 256 + k0 + kk];
            float4 bv0 = *(const float4*)(sW + kk * 256 + colBase);
            float4 bv1 = *(const float4*)(sW + kk * 256 + colBase + 4);
            float bvv[8] = {bv0.x, bv0.y, bv0.z, bv0.w, bv1.x, bv1.y, bv1.z, bv1.w};
            #pragma unroll
            for (int im = 0; im < 8; ++im)
                #pragma unroll
                for (int in = 0; in < 8; ++in)
                    acc[im * 8 + in] = fmaf(av[im], bvv[in], acc[im * 8 + in]);
        }
        __syncthreads();   // sW + sAct reads done -> safe to restage / (after loop) rewrite
    }

    float bb[8];
    #pragma unroll
    for (int in = 0; in < 8; ++in) bb[in] = __ldg(bias + colBase + in);

    #pragma unroll
    for (int im = 0; im < 8; ++im) {
        float tmp[8];
        #pragma unroll
        for (int in = 0; in < 8; ++in) {
            float v = acc[im * 8 + in] + bb[in];
            if (DOGELU) v = gelu_exact(v);
            tmp[in] = v;
        }
        *(float4*)(sAct + (rowBase + im) * 256 + colBase)     = make_float4(tmp[0], tmp[1], tmp[2], tmp[3]);
        *(float4*)(sAct + (rowBase + im) * 256 + colBase + 4) = make_float4(tmp[4], tmp[5], tmp[6], tmp[7]);
    }
    __syncthreads();
}

__global__ void __launch_bounds__(TPB)
mlp_kernel(const float* __restrict__ Fg,
           const float* __restrict__ W1,
           const float* __restrict__ W2, const float* __restrict__ b2,
           const float* __restrict__ W3, const float* __restrict__ b3,
           const float* __restrict__ W4, const float* __restrict__ b4,
           const float* __restrict__ W5, const float* __restrict__ b5,
           float* __restrict__ outg, int B)
{
    extern __shared__ float smem[];
    float* sAct = smem;                    // 64 * 256
    float* sW   = smem + BM * 256;         // 2304 (W tile / W5)
    float* sOut = sW + 2304;               // 64 * 9

    const int tid = threadIdx.x;
    const int blockRow = blockIdx.x * BM;

    // stage features: 64 rows * 32 floats, contiguous in g_feats
    {
        const float4* src = (const float4*)(g_feats + (size_t)blockRow * 32);
        for (int v = tid; v < BM * 8; v += TPB) {
            float4 val = src[v];
            int row = v >> 3, k4 = v & 7;
            ((float4*)(sAct + row * 256))[k4] = val;
        }
    }
    __syncthreads();

    layer_pass<true>(W1, g_c1, 32, 25, sAct, sW, tid);   // layer 1 (latent folded into g_c1)
    layer_pass<true>(W2, b2, 256, 256, sAct, sW, tid);
    layer_pass<true>(W3, b3, 256, 256, sAct, sW, tid);
    layer_pass<true>(W4, b4, 256, 256, sAct, sW, tid);

    // layer 5: [64,256] @ [256,9] + b5
    {
        const float4* src = (const float4*)W5;           // 2304 floats = 576 float4
        for (int v = tid; v < 576; v += TPB) ((float4*)sW)[v] = src[v];
        __syncthreads();
        for (int idx = tid; idx < BM * 9; idx += TPB) {
            int m = idx / 9, n = idx - m * 9;
            const float* arow = sAct + m * 256;
            float s = __ldg(b5 + n);
            #pragma unroll 4
            for (int k = 0; k < 256; ++k)
                s = fmaf(arow[k], sW[k * 9 + n], s);
            sOut[idx] = s;
        }
        __syncthreads();
    }

    // epilogue: symmetrize, P = R*xs, cauchy = P * F^T
    if (tid < BM) {
        int i = blockRow + tid;
        if (i < B) {
            float x[9];
            #pragma unroll
            for (int j = 0; j < 9; ++j) x[j] = sOut[tid * 9 + j];
            float xs[9];
            xs[0] = x[0]; xs[4] = x[4]; xs[8] = x[8];
            xs[1] = xs[3] = 0.5f * (x[1] + x[3]);
            xs[2] = xs[6] = 0.5f * (x[2] + x[6]);
            xs[5] = xs[7] = 0.5f * (x[5] + x[7]);

            float R[9], Ff[9], P[9];
            #pragma unroll
            for (int k = 0; k < 9; ++k) R[k]  = g_R[(size_t)i * 9 + k];
            #pragma unroll
            for (int k = 0; k < 9; ++k) Ff[k] = Fg[(size_t)i * 9 + k];

            #pragma unroll
            for (int rI = 0; rI < 3; ++rI)
                #pragma unroll
                for (int cI = 0; cI < 3; ++cI)
                    P[rI * 3 + cI] = R[rI*3+0]*xs[0*3+cI] + R[rI*3+1]*xs[1*3+cI] + R[rI*3+2]*xs[2*3+cI];

            #pragma unroll
            for (int rI = 0; rI < 3; ++rI)
                #pragma unroll
                for (int cI = 0; cI < 3; ++cI) {
                    // cauchy[r][c] = sum_k P[r][k] * Ft[k][c] = sum_k P[r][k] * F[c][k]
                    float v = P[rI*3+0]*Ff[cI*3+0] + P[rI*3+1]*Ff[cI*3+1] + P[rI*3+2]*Ff[cI*3+2];
                    outg[(size_t)i * 9 + rI * 3 + cI] = v;
                }
        }
    }
}

// ---------------------------------------------------------------------------
extern "C" void kernel_launch(void* const* d_in, const int* in_sizes, int n_in,
                              void* d_out, int out_size) {
    const float* F    = (const float*)d_in[0];
    const float* C    = (const float*)d_in[1];
    const float* emb  = (const float*)d_in[2];
    const int*   traj = (const int*)  d_in[3];
    const float* W1 = (const float*)d_in[4];
    const float* b1 = (const float*)d_in[5];
    const float* W2 = (const float*)d_in[6];
    const float* b2 = (const float*)d_in[7];
    const float* W3 = (const float*)d_in[8];
    const float* b3 = (const float*)d_in[9];
    const float* W4 = (const float*)d_in[10];
    const float* b4 = (const float*)d_in[11];
    const float* W5 = (const float*)d_in[12];
    const float* b5 = (const float*)d_in[13];
    float* out = (float*)d_out;

    int B = in_sizes[0] / 9;
    if (B > MAXB) B = MAXB;

    c1_kernel<<<1, 256>>>(emb, traj, W1, b1);
    feat_kernel<<<(B + 127) / 128, 128>>>(F, C, B);

    size_t SMEM = (size_t)(BM * 256 + 2304 + BM * 9) * sizeof(float);
    cudaFuncSetAttribute(mlp_kernel, cudaFuncAttributeMaxDynamicSharedMemorySize, (int)SMEM);
    mlp_kernel<<<(B + BM - 1) / BM, TPB, SMEM>>>(F, W1, W2, b2, W3, b3, W4, b4, W5, b5, out, B);
}

// round 3
// speedup vs baseline: 3.8165x; 3.8165x over previous
#include <cuda_runtime.h>
#include <cuda_bf16.h>
#include <math.h>
#include <stdint.h>

#define MAXB    262144
#define TILE_M  128
#define THREADS 256
#define EPSF    1e-6f

#define NCHUNK   26
#define CHUNK_U4 2048
#define BUFSZ    32768
#define SA_OFF   1024
#define SA_SPLIT 65536
#define BUF_OFF  (SA_OFF + 2*SA_SPLIT)      // 132096
#define SMEM_TOTAL (BUF_OFF + 2*BUFSZ)      // 197632

// ---------------- device globals ----------------
__device__ __align__(128) uint4 g_wimg[NCHUNK * CHUNK_U4];   // 832KB b-frag weight image
__device__ float g_c1[256];                                  // b1 + latent @ W1[25:153]
__device__ float g_R[MAXB * 9];                              // polar rotations

// ---------------- helpers ----------------
__device__ __forceinline__ uint32_t smem_to_u32(const void* p) {
    uint32_t a;
    asm("{ .reg .u64 t; cvta.to.shared.u64 t, %1; cvt.u32.u64 %0, t; }" : "=r"(a) : "l"(p));
    return a;
}

// pack two fp32 -> bf16x2: 'lo' goes to lower half (k even), 'hi' to upper (k odd)
__device__ __forceinline__ uint32_t packbf2(float lo, float hi) {
    uint32_t r;
    asm("cvt.rn.bf16x2.f32 %0, %1, %2;" : "=r"(r) : "f"(hi), "f"(lo));
    return r;
}

// hi/lo split of a float pair into two bf16x2 words
__device__ __forceinline__ void split2(float a, float b, uint32_t& h, uint32_t& l) {
    h = packbf2(a, b);
    float ha = __uint_as_float(h << 16);
    float hb = __uint_as_float(h & 0xffff0000u);
    l = packbf2(a - ha, b - hb);
}

__device__ __forceinline__ void mma_bf16(float* d, const uint4& a, uint32_t b0, uint32_t b1) {
    asm volatile("mma.sync.aligned.m16n8k16.row.col.f32.bf16.bf16.f32 "
        "{%0,%1,%2,%3}, {%4,%5,%6,%7}, {%8,%9}, {%0,%1,%2,%3};"
        : "+f"(d[0]), "+f"(d[1]), "+f"(d[2]), "+f"(d[3])
        : "r"(a.x), "r"(a.y), "r"(a.z), "r"(a.w), "r"(b0), "r"(b1));
}

__device__ __forceinline__ void cpasync16(uint32_t dst, const void* src) {
    asm volatile("cp.async.cg.shared.global [%0], [%1], 16;" :: "r"(dst), "l"(src));
}
#define CP_COMMIT() asm volatile("cp.async.commit_group;" ::: "memory")
#define CP_WAIT1()  asm volatile("cp.async.wait_group 1;" ::: "memory")
#define CP_WAIT0()  asm volatile("cp.async.wait_group 0;" ::: "memory")

__device__ __forceinline__ float gelu_exact(float x) {
    return 0.5f * x * (1.0f + erff(x * 0.70710678118654752f));
}

// ---------------- prep kernels ----------------
__global__ void c1_kernel(const float* __restrict__ emb, const int* __restrict__ traj,
                          const float* __restrict__ W1, const float* __restrict__ b1) {
    int n = threadIdx.x;
    const float* lat = emb + traj[0] * 128;
    float s = b1[n];
    #pragma unroll 4
    for (int d = 0; d < 128; ++d)
        s = fmaf(__ldg(lat + d), __ldg(W1 + (25 + d) * 256 + n), s);
    g_c1[n] = s;
}

// Build b-frag weight image. Entry (per chunk of 2048 uint4):
//   layers 1-4: idx = (kt&1)*1024 + nt*32 + lane       (chunk holds kt pair)
//   layer 5   : idx = kt*64 + nt*32 + lane, tail zero  (one chunk: 16 kt x 2 nt)
// uint4 = { hi(k0,k0+1), hi(k0+8,k0+9), lo(k0,k0+1), lo(k0+8,k0+9) },
//   k0 = kt*16 + 2*(lane&3), n = nt*8 + (lane>>2)
__global__ void wprep_kernel(const float* __restrict__ W1, const float* __restrict__ W2,
                             const float* __restrict__ W3, const float* __restrict__ W4,
                             const float* __restrict__ W5) {
    int e = blockIdx.x * blockDim.x + threadIdx.x;
    if (e >= NCHUNK * CHUNK_U4) return;
    int gc = e >> 11, within = e & 2047;
    const float* W; int Kreal, Nreal, ld, kt, nt, lane;
    if (gc == 0) {
        W = W1; Kreal = 25; Nreal = 256; ld = 256;
        kt = within >> 10; int rem = within & 1023; nt = rem >> 5; lane = rem & 31;
    } else if (gc <= 8) {
        W = W2; Kreal = 256; Nreal = 256; ld = 256;
        kt = (gc - 1) * 2 + (within >> 10); int rem = within & 1023; nt = rem >> 5; lane = rem & 31;
    } else if (gc <= 16) {
        W = W3; Kreal = 256; Nreal = 256; ld = 256;
        kt = (gc - 9) * 2 + (within >> 10); int rem = within & 1023; nt = rem >> 5; lane = rem & 31;
    } else if (gc <= 24) {
        W = W4; Kreal = 256; Nreal = 256; ld = 256;
        kt = (gc - 17) * 2 + (within >> 10); int rem = within & 1023; nt = rem >> 5; lane = rem & 31;
    } else {
        if (within >= 1024) { g_wimg[e] = make_uint4(0u, 0u, 0u, 0u); return; }
        W = W5; Kreal = 256; Nreal = 9; ld = 9;
        kt = within >> 6; nt = (within >> 5) & 1; lane = within & 31;
    }
    int q = lane & 3, n = nt * 8 + (lane >> 2);
    int k0 = kt * 16 + 2 * q;
    float v00 = (k0     < Kreal && n < Nreal) ? W[(size_t)(k0    ) * ld + n] : 0.f;
    float v01 = (k0 + 1 < Kreal && n < Nreal) ? W[(size_t)(k0 + 1) * ld + n] : 0.f;
    float v10 = (k0 + 8 < Kreal && n < Nreal) ? W[(size_t)(k0 + 8) * ld + n] : 0.f;
    float v11 = (k0 + 9 < Kreal && n < Nreal) ? W[(size_t)(k0 + 9) * ld + n] : 0.f;
    uint4 o;
    uint32_t h, l;
    split2(v00, v01, h, l); o.x = h; o.z = l;
    split2(v10, v11, h, l); o.y = h; o.w = l;
    g_wimg[e] = o;
}

// ---------------- main kernel ----------------
__global__ void __launch_bounds__(THREADS, 1)
mlp_mma_kernel(const float* __restrict__ Fg, const float* __restrict__ Cg,
               const float* __restrict__ b2, const float* __restrict__ b3,
               const float* __restrict__ b4, const float* __restrict__ b5,
               float* __restrict__ outg, int B)
{
    extern __shared__ __align__(1024) char smem[];
    const uint32_t sbase = smem_to_u32(smem);
    const int tid  = threadIdx.x;
    const int lane = tid & 31;
    const int wid  = tid >> 5;
    const int mb   = wid & 3;        // m row-block (32 rows)
    const int nh   = wid >> 2;       // n half (128 cols)
    const int q    = lane & 3;
    const int blockRow = blockIdx.x * TILE_M;

    uint4* sAhi = (uint4*)(smem + SA_OFF);
    uint4* sAlo = (uint4*)(smem + SA_OFF + SA_SPLIT);

    // issue chunk 0 (cooperative: 2048 uint4 over 256 threads)
    {
        const uint4* src = g_wimg;
        uint32_t dst = sbase + BUF_OFF;
        #pragma unroll
        for (int rr = 0; rr < 8; ++rr) {
            int idx = rr * 256 + tid;
            cpasync16(dst + idx * 16, src + idx);
        }
        CP_COMMIT();
    }

    // ---------------- front-end (threads 0-127; feats -> buf1 scratch) -------
    float* feats_s = (float*)(smem + BUF_OFF + BUFSZ);   // [128][33]
    if (tid < TILE_M) {
        int ig = blockRow + tid; if (ig >= B) ig = B - 1;
        float f[9], r[9];
        #pragma unroll
        for (int k = 0; k < 9; ++k) { f[k] = Fg[(size_t)ig * 9 + k]; r[k] = f[k]; }
        #pragma unroll
        for (int it = 0; it < 5; ++it) {
            float c00 = r[4]*r[8]-r[5]*r[7], c01 = r[5]*r[6]-r[3]*r[8], c02 = r[3]*r[7]-r[4]*r[6];
            float c10 = r[2]*r[7]-r[1]*r[8], c11 = r[0]*r[8]-r[2]*r[6], c12 = r[1]*r[6]-r[0]*r[7];
            float c20 = r[1]*r[5]-r[2]*r[4], c21 = r[2]*r[3]-r[0]*r[5], c22 = r[0]*r[4]-r[1]*r[3];
            float det = r[0]*c00 + r[1]*c01 + r[2]*c02;
            float ad  = fmaxf(fabsf(det), 1e-30f);
            float mu  = rcbrtf(ad);
            float s2  = 0.5f * mu;
            float s3  = 0.5f / (mu * det);
            float n0=s2*r[0]+s3*c00, n1=s2*r[1]+s3*c01, n2=s2*r[2]+s3*c02;
            float n3=s2*r[3]+s3*c10, n4=s2*r[4]+s3*c11, n5=s2*r[5]+s3*c12;
            float n6=s2*r[6]+s3*c20, n7=s2*r[7]+s3*c21, n8=s2*r[8]+s3*c22;
            r[0]=n0;r[1]=n1;r[2]=n2;r[3]=n3;r[4]=n4;r[5]=n5;r[6]=n6;r[7]=n7;r[8]=n8;
        }
        float a00=f[0]*f[0]+f[3]*f[3]+f[6]*f[6];
        float a01=f[0]*f[1]+f[3]*f[4]+f[6]*f[7];
        float a02=f[0]*f[2]+f[3]*f[5]+f[6]*f[8];
        float a11=f[1]*f[1]+f[4]*f[4]+f[7]*f[7];
        float a12=f[1]*f[2]+f[4]*f[5]+f[7]*f[8];
        float a22=f[2]*f[2]+f[5]*f[5]+f[8]*f[8];
        float qv = (a00+a11+a22)*(1.0f/3.0f);
        float d0 = a00-qv, d1 = a11-qv, d2 = a22-qv;
        float p2 = d0*d0+d1*d1+d2*d2+2.0f*(a01*a01+a02*a02+a12*a12);
        float e1,e2,e3;
        if (p2 < 1e-18f) { e1=e2=e3=qv; }
        else {
            float p = sqrtf(p2*(1.0f/6.0f)), invp = 1.0f/p;
            float b00=d0*invp,b11=d1*invp,b22=d2*invp;
            float b01=a01*invp,b02=a02*invp,b12=a12*invp;
            float detB = b00*(b11*b22-b12*b12)-b01*(b01*b22-b12*b02)+b02*(b01*b12-b11*b02);
            float rr = fminf(fmaxf(0.5f*detB,-1.0f),1.0f);
            float phi = acosf(rr)*(1.0f/3.0f);
            e1 = qv+2.0f*p*cosf(phi);
            e3 = qv+2.0f*p*cosf(phi+2.09439510239319549f);
            e2 = 3.0f*qv-e1-e3;
        }
        float detF = f[0]*(f[4]*f[8]-f[5]*f[7]) - f[1]*(f[3]*f[8]-f[5]*f[6]) + f[2]*(f[3]*f[7]-f[4]*f[6]);
        float f00c = fmaxf(f[0], EPSF);
        float ft[32];
        ft[0]=sqrtf(fmaxf(e1,0.f))-1.f; ft[1]=sqrtf(fmaxf(e2,0.f))-1.f; ft[2]=sqrtf(fmaxf(e3,0.f))-1.f;
        ft[3]=a00-1.f; ft[4]=a01; ft[5]=a02;
        ft[6]=a01; ft[7]=a11-1.f; ft[8]=a12;
        ft[9]=a02; ft[10]=a12; ft[11]=a22-1.f;
        ft[12]=detF-1.f; ft[13]=logf(detF)-1.f;
        ft[14]=f00c-1.f; ft[15]=logf(f00c)-1.f;
        #pragma unroll
        for (int j = 0; j < 9; ++j) ft[16+j] = Cg[(size_t)ig*9+j];
        #pragma unroll
        for (int j = 25; j < 32; ++j) ft[j] = 0.0f;
        #pragma unroll
        for (int k = 0; k < 32; ++k) feats_s[tid * 33 + k] = ft[k];
        #pragma unroll
        for (int k = 0; k < 9; ++k) g_R[(size_t)ig * 9 + k] = r[k];
    }
    __syncthreads();

    // ---------------- build L1 A-frags (all 8 warps; warp handles kt=nh) -----
    {
        int kt = nh;   // 0 or 1
        #pragma unroll
        for (int m = 0; m < 2; ++m) {
            int mtg = mb * 2 + m;
            uint4 h4, l4;
            #pragma unroll
            for (int i = 0; i < 2; ++i) {
                int row = mtg * 16 + (lane >> 2) + 8 * i;
                #pragma unroll
                for (int s = 0; s < 2; ++s) {
                    int k = kt * 16 + 2 * q + 8 * s;
                    float va = feats_s[row * 33 + k];
                    float vb = feats_s[row * 33 + k + 1];
                    uint32_t hh, ll; split2(va, vb, hh, ll);
                    // word slot: (i0,s0)=x (i1,s0)=y (i0,s1)=z (i1,s1)=w
                    if (i == 0 && s == 0) { h4.x = hh; l4.x = ll; }
                    if (i == 1 && s == 0) { h4.y = hh; l4.y = ll; }
                    if (i == 0 && s == 1) { h4.z = hh; l4.z = ll; }
                    if (i == 1 && s == 1) { h4.w = hh; l4.w = ll; }
                }
            }
            sAhi[(mtg * 16 + kt) * 32 + lane] = h4;
            sAlo[(mtg * 16 + kt) * 32 + lane] = l4;
        }
    }
    __syncthreads();

    // issue chunk 1 (into buf1, overwrites feats scratch)
    {
        const uint4* src = g_wimg + CHUNK_U4;
        uint32_t dst = sbase + BUF_OFF + BUFSZ;
        #pragma unroll
        for (int rr = 0; rr < 8; ++rr) {
            int idx = rr * 256 + tid;
            cpasync16(dst + idx * 16, src + idx);
        }
        CP_COMMIT();
    }

    // ---------------- layer loop --------------------------------------------
    float acc[2][16][4];
    #pragma unroll
    for (int m = 0; m < 2; ++m)
        #pragma unroll
        for (int t = 0; t < 16; ++t)
            #pragma unroll
            for (int rr2 = 0; rr2 < 4; ++rr2) acc[m][t][rr2] = 0.0f;

    const int nchunksA[4] = {1, 8, 8, 8};
    const float* biasA[4] = {g_c1, b2, b3, b4};

    int gc = 0;
    for (int L = 0; L < 4; ++L) {
        const int nc = nchunksA[L];
        const float* bias = biasA[L];
        for (int c = 0; c < nc; ++c, ++gc) {
            CP_WAIT1();
            __syncthreads();
            const uint4* buf = (const uint4*)(smem + BUF_OFF + (gc & 1) * BUFSZ);
            #pragma unroll
            for (int half = 0; half < 2; ++half) {
                int kt = c * 2 + half;
                const uint4* aph = sAhi + ((mb * 2) * 16 + kt) * 32 + lane;
                const uint4* apl = sAlo + ((mb * 2) * 16 + kt) * 32 + lane;
                uint4 ah0 = aph[0], ah1 = aph[512];
                uint4 al0 = apl[0], al1 = apl[512];
                const uint4* bp = buf + half * 1024 + (nh * 16) * 32 + lane;
                #pragma unroll
                for (int nt = 0; nt < 16; ++nt) {
                    uint4 b = bp[nt * 32];
                    mma_bf16(acc[0][nt], ah0, b.x, b.y);
                    mma_bf16(acc[1][nt], ah1, b.x, b.y);
                    mma_bf16(acc[0][nt], al0, b.x, b.y);
                    mma_bf16(acc[1][nt], al1, b.x, b.y);
                    mma_bf16(acc[0][nt], ah0, b.z, b.w);
                    mma_bf16(acc[1][nt], ah1, b.z, b.w);
                }
            }
            __syncthreads();
            if (gc + 2 < NCHUNK) {
                const uint4* src = g_wimg + (size_t)(gc + 2) * CHUNK_U4;
                uint32_t dst = sbase + BUF_OFF + ((gc + 2) & 1) * BUFSZ;
                #pragma unroll
                for (int rr = 0; rr < 8; ++rr) {
                    int idx = rr * 256 + tid;
                    cpasync16(dst + idx * 16, src + idx);
                }
                CP_COMMIT();
            }
        }

        // epilogue: bias + exact GELU + split -> A-frags for next layer
        #pragma unroll
        for (int m = 0; m < 2; ++m) {
            int mtg = mb * 2 + m;
            #pragma unroll
            for (int tt = 0; tt < 8; ++tt) {
                float g[2][4];
                #pragma unroll
                for (int u = 0; u < 2; ++u) {
                    int t = 2 * tt + u;
                    #pragma unroll
                    for (int rr2 = 0; rr2 < 4; ++rr2) {
                        int col = nh * 128 + t * 8 + 2 * q + (rr2 & 1);
                        float v = acc[m][t][rr2] + __ldg(bias + col);
                        g[u][rr2] = gelu_exact(v);
                        acc[m][t][rr2] = 0.0f;          // reset for next layer
                    }
                }
                uint4 h4, l4; uint32_t hh, ll;
                split2(g[0][0], g[0][1], hh, ll); h4.x = hh; l4.x = ll;
                split2(g[0][2], g[0][3], hh, ll); h4.y = hh; l4.y = ll;
                split2(g[1][0], g[1][1], hh, ll); h4.z = hh; l4.z = ll;
                split2(g[1][2], g[1][3], hh, ll); h4.w = hh; l4.w = ll;
                int kt_out = nh * 8 + tt;
                sAhi[(mtg * 16 + kt_out) * 32 + lane] = h4;
                sAlo[(mtg * 16 + kt_out) * 32 + lane] = l4;
            }
        }
        // next chunk's wait+syncthreads orders these writes before the reads
    }

    // ---------------- layer 5: [128,256] @ [256,16] via mma ------------------
    CP_WAIT0();
    __syncthreads();
    if (nh == 0) {
        float acc5[2][2][4];
        #pragma unroll
        for (int m = 0; m < 2; ++m)
            #pragma unroll
            for (int t = 0; t < 2; ++t)
                #pragma unroll
                for (int rr2 = 0; rr2 < 4; ++rr2) acc5[m][t][rr2] = 0.0f;
        const uint4* buf = (const uint4*)(smem + BUF_OFF + BUFSZ);   // chunk 25 -> buf1
        #pragma unroll
        for (int kt = 0; kt < 16; ++kt) {
            const uint4* aph = sAhi + ((mb * 2) * 16 + kt) * 32 + lane;
            const uint4* apl = sAlo + ((mb * 2) * 16 + kt) * 32 + lane;
            uint4 ah0 = aph[0], ah1 = aph[512];
            uint4 al0 = apl[0], al1 = apl[512];
            #pragma unroll
            for (int nt = 0; nt < 2; ++nt) {
                uint4 b = buf[kt * 64 + nt * 32 + lane];
                mma_bf16(acc5[0][nt], ah0, b.x, b.y);
                mma_bf16(acc5[1][nt], ah1, b.x, b.y);
                mma_bf16(acc5[0][nt], al0, b.x, b.y);
                mma_bf16(acc5[1][nt], al1, b.x, b.y);
                mma_bf16(acc5[0][nt], ah0, b.z, b.w);
                mma_bf16(acc5[1][nt], ah1, b.z, b.w);
            }
        }
        // scatter to plain [128][18] in buf0
        float* plain = (float*)(smem + BUF_OFF);
        #pragma unroll
        for (int m = 0; m < 2; ++m) {
            int mtg = mb * 2 + m;
            #pragma unroll
            for (int t = 0; t < 2; ++t) {
                #pragma unroll
                for (int i = 0; i < 2; ++i) {
                    int row = mtg * 16 + (lane >> 2) + 8 * i;
                    int col = t * 8 + 2 * q;
                    plain[row * 18 + col]     = acc5[m][t][2 * i];
                    plain[row * 18 + col + 1] = acc5[m][t][2 * i + 1];
                }
            }
        }
    }
    __syncthreads();

    // ---------------- final epilogue -----------------------------------------
    if (tid < TILE_M) {
        int ig = blockRow + tid;
        if (ig < B) {
            const float* plain = (const float*)(smem + BUF_OFF);
            float x[9];
            #pragma unroll
            for (int n = 0; n < 9; ++n) x[n] = plain[tid * 18 + n] + __ldg(b5 + n);
            float xs[9];
            xs[0]=x[0]; xs[4]=x[4]; xs[8]=x[8];
            xs[1]=xs[3]=0.5f*(x[1]+x[3]);
            xs[2]=xs[6]=0.5f*(x[2]+x[6]);
            xs[5]=xs[7]=0.5f*(x[5]+x[7]);
            float R[9], Ff[9], P[9];
            #pragma unroll
            for (int k = 0; k < 9; ++k) R[k]  = g_R[(size_t)ig * 9 + k];
            #pragma unroll
            for (int k = 0; k < 9; ++k) Ff[k] = Fg[(size_t)ig * 9 + k];
            #pragma unroll
            for (int rI = 0; rI < 3; ++rI)
                #pragma unroll
                for (int cI = 0; cI < 3; ++cI)
                    P[rI*3+cI] = R[rI*3+0]*xs[0*3+cI] + R[rI*3+1]*xs[1*3+cI] + R[rI*3+2]*xs[2*3+cI];
            #pragma unroll
            for (int rI = 0; rI < 3; ++rI)
                #pragma unroll
                for (int cI = 0; cI < 3; ++cI)
                    outg[(size_t)ig*9 + rI*3 + cI] =
                        P[rI*3+0]*Ff[cI*3+0] + P[rI*3+1]*Ff[cI*3+1] + P[rI*3+2]*Ff[cI*3+2];
        }
    }
}

// ---------------- launch ----------------
extern "C" void kernel_launch(void* const* d_in, const int* in_sizes, int n_in,
                              void* d_out, int out_size) {
    const float* F    = (const float*)d_in[0];
    const float* C    = (const float*)d_in[1];
    const float* emb  = (const float*)d_in[2];
    const int*   traj = (const int*)  d_in[3];
    const float* W1 = (const float*)d_in[4];
    const float* b1 = (const float*)d_in[5];
    const float* W2 = (const float*)d_in[6];
    const float* b2 = (const float*)d_in[7];
    const float* W3 = (const float*)d_in[8];
    const float* b3 = (const float*)d_in[9];
    const float* W4 = (const float*)d_in[10];
    const float* b4 = (const float*)d_in[11];
    const float* W5 = (const float*)d_in[12];
    const float* b5 = (const float*)d_in[13];
    float* out = (float*)d_out;

    int B = in_sizes[0] / 9;
    if (B > MAXB) B = MAXB;

    c1_kernel<<<1, 256>>>(emb, traj, W1, b1);
    wprep_kernel<<<(NCHUNK * CHUNK_U4 + 255) / 256, 256>>>(W1, W2, W3, W4, W5);

    cudaFuncSetAttribute(mlp_mma_kernel, cudaFuncAttributeMaxDynamicSharedMemorySize, SMEM_TOTAL);
    int nblk = (B + TILE_M - 1) / TILE_M;
    mlp_mma_kernel<<<nblk, THREADS, SMEM_TOTAL>>>(F, C, b2, b3, b4, b5, out, B);
}